// round 16
// baseline (speedup 1.0000x reference)
#include <cuda_runtime.h>
#include <math.h>

#define N_EDGES_C 1000000
#define TILE_E 64

// Aliased smem layout (floats), feature-major [F][64]:
//   A : [128][64]  offset 0        (h1 / r2)
//   T : [192][64]  offset 8192     (triplets)
//     after e1: B [64][64] at T+0, ENC [32][64] at T+4096 (alive to end)
// 80KB/CTA -> 2 CTAs = 160KB smem, ~68KB L1D carveout for streamed weights.
#define SMEM_FLOATS (8192 + 12288)
#define SMEM_BYTES (SMEM_FLOATS * 4)

// Fused layer: C[64][F_OUT] = act(A[64][F_IN] @ W[F_IN][F_OUT] + b)
// Asm feature-major [F_IN][64]. 128 threads: 16 e-groups (4 consecutive edges)
// x 8 f-groups (NF = F_OUT/8 consecutive features). Per warp per k:
// 1 LDS.128 + NF/4 LDG.128 (2 addresses) vs 2*NF FFMA-cyc -> FMA-bound.
template<int F_IN, int F_OUT, bool RELU, bool SMOUT, bool GOUT>
__device__ __forceinline__ void gemm_layer(
    const float* __restrict__ Asm, const float* __restrict__ W,
    const float* __restrict__ bias, float* __restrict__ Csm,
    float* __restrict__ gout, int tid)
{
    constexpr int NF = F_OUT / 8;
    static_assert((NF & 3) == 0, "NF multiple of 4");
    const int e0 = (tid & 15) << 2;
    const int f0 = (tid >> 4) * NF;

    float acc[NF][4];
#pragma unroll
    for (int j = 0; j < NF; ++j) {
        const float b = __ldg(bias + f0 + j);
        acc[j][0] = b; acc[j][1] = b; acc[j][2] = b; acc[j][3] = b;
    }

#pragma unroll 2
    for (int k = 0; k < F_IN; ++k) {
        const float4 av = *reinterpret_cast<const float4*>(Asm + k * TILE_E + e0);
        const float* wr = W + k * F_OUT + f0;
#pragma unroll
        for (int u = 0; u < NF / 4; ++u) {
            const float4 w4 = __ldg(reinterpret_cast<const float4*>(wr) + u);
            acc[4*u+0][0] += av.x * w4.x; acc[4*u+0][1] += av.y * w4.x;
            acc[4*u+0][2] += av.z * w4.x; acc[4*u+0][3] += av.w * w4.x;
            acc[4*u+1][0] += av.x * w4.y; acc[4*u+1][1] += av.y * w4.y;
            acc[4*u+1][2] += av.z * w4.y; acc[4*u+1][3] += av.w * w4.y;
            acc[4*u+2][0] += av.x * w4.z; acc[4*u+2][1] += av.y * w4.z;
            acc[4*u+2][2] += av.z * w4.z; acc[4*u+2][3] += av.w * w4.z;
            acc[4*u+3][0] += av.x * w4.w; acc[4*u+3][1] += av.y * w4.w;
            acc[4*u+3][2] += av.z * w4.w; acc[4*u+3][3] += av.w * w4.w;
        }
    }

    if constexpr (RELU) {
#pragma unroll
        for (int j = 0; j < NF; ++j)
#pragma unroll
            for (int i = 0; i < 4; ++i)
                acc[j][i] = fmaxf(acc[j][i], 0.0f);
    }

    if constexpr (SMOUT) {
#pragma unroll
        for (int j = 0; j < NF; ++j)
            *reinterpret_cast<float4*>(Csm + (f0 + j) * TILE_E + e0) =
                make_float4(acc[j][0], acc[j][1], acc[j][2], acc[j][3]);
    }

    if constexpr (GOUT) {
#pragma unroll
        for (int i = 0; i < 4; ++i) {
            float* gp = gout + (size_t)(e0 + i) * F_OUT + f0;
#pragma unroll
            for (int u = 0; u < NF / 4; ++u)
                *reinterpret_cast<float4*>(gp + 4 * u) =
                    make_float4(acc[4*u+0][i], acc[4*u+1][i],
                                acc[4*u+2][i], acc[4*u+3][i]);
        }
    }
}

__global__ void __launch_bounds__(128, 2)
gnn_fused_kernel(
    const float* __restrict__ x,
    const float* __restrict__ ea,
    const int* __restrict__ ei,     // int32 (jax default, no x64)
    const float* __restrict__ W_e1, const float* __restrict__ b_e1,
    const float* __restrict__ W_e2, const float* __restrict__ b_e2,
    const float* __restrict__ W_e3, const float* __restrict__ b_e3,
    const float* __restrict__ W_d1, const float* __restrict__ b_d1,
    const float* __restrict__ W_d2, const float* __restrict__ b_d2,
    const float* __restrict__ W_d3, const float* __restrict__ b_d3,
    const float* __restrict__ W_s1, const float* __restrict__ b_s1,
    const float* __restrict__ W_s2, const float* __restrict__ b_s2,
    float* __restrict__ enc_out,    // [E,32]
    float* __restrict__ rec_out,    // [E,192]
    float* __restrict__ trip_out,   // [E,192]
    float* __restrict__ score_out)  // [E,1]
{
    extern __shared__ float smem[];
    float* Asm   = smem;                 // [128][64]
    float* Tsm   = smem + 128 * TILE_E;  // [192][64]; aliased after e1:
    float* Bsm   = Tsm;                  //   [64][64]
    float* ENCsm = Tsm + 64 * TILE_E;    //   [32][64]  (alive to kernel end)

    const int tid = threadIdx.x;
    const long long ebase = (long long)blockIdx.x * TILE_E;

    // ---- Gather: triplets -> smem (feature-major) + trip_out (row-major).
    //      128 threads: 2 threads per edge, 24 float4 each.
    {
        const int el = tid >> 1;   // 0..63 edge within tile
        const int r  = tid & 1;    // 2 threads per edge
        const long long eg = ebase + el;
        const int s = __ldg(ei + eg);
        const int d = __ldg(ei + N_EDGES_C + eg);
        const float4* srcp = reinterpret_cast<const float4*>(x + (size_t)s * 64);
        const float4* eap  = reinterpret_cast<const float4*>(ea + (size_t)eg * 64);
        const float4* dstp = reinterpret_cast<const float4*>(x + (size_t)d * 64);
        float* top = trip_out + (size_t)eg * 192;
#pragma unroll
        for (int m = 0; m < 24; ++m) {
            const int q = r * 24 + m;  // float4 index in [0,48)
            float4 v;
            if (q < 16)      v = __ldg(srcp + q);
            else if (q < 32) v = __ldg(eap + (q - 16));
            else             v = __ldg(dstp + (q - 32));
            const int k = q * 4;
            Tsm[(k + 0) * TILE_E + el] = v.x;
            Tsm[(k + 1) * TILE_E + el] = v.y;
            Tsm[(k + 2) * TILE_E + el] = v.z;
            Tsm[(k + 3) * TILE_E + el] = v.w;
            *reinterpret_cast<float4*>(top + k) = v;
        }
    }
    __syncthreads();

    // ---- Encoder
    gemm_layer<192, 128, true,  true,  false>(Tsm, W_e1, b_e1, Asm, nullptr, tid);
    __syncthreads();   // T dead from here; B/ENC alias into it
    gemm_layer<128, 64,  true,  true,  false>(Asm, W_e2, b_e2, Bsm, nullptr, tid);
    __syncthreads();
    gemm_layer<64,  32,  false, true,  true >(Bsm, W_e3, b_e3, ENCsm,
                                              enc_out + ebase * 32, tid);
    __syncthreads();

    // ---- Decoder (d1 overwrites B region; ENC stays intact)
    gemm_layer<32,  64,  true,  true,  false>(ENCsm, W_d1, b_d1, Bsm, nullptr, tid);
    __syncthreads();
    gemm_layer<64,  128, true,  true,  false>(Bsm, W_d2, b_d2, Asm, nullptr, tid);
    __syncthreads();
    gemm_layer<128, 192, false, false, true >(Asm, W_d3, b_d3, nullptr,
                                              rec_out + ebase * 192, tid);

    // ---- Scorer in registers from ENC (no extra barriers; ENC untouched).
    if (tid < TILE_E) {
        float e[32];
#pragma unroll
        for (int k = 0; k < 32; ++k)
            e[k] = ENCsm[k * TILE_E + tid];
        float acc = __ldg(b_s2);
#pragma unroll
        for (int j = 0; j < 16; ++j) {
            float hs = __ldg(b_s1 + j);
#pragma unroll
            for (int k = 0; k < 32; ++k)
                hs += e[k] * __ldg(W_s1 + k * 16 + j);
            hs = fmaxf(hs, 0.0f);
            acc += hs * __ldg(W_s2 + j);
        }
        score_out[ebase + tid] = 1.0f / (1.0f + expf(-acc));
    }
}

extern "C" void kernel_launch(void* const* d_in, const int* in_sizes, int n_in,
                              void* d_out, int out_size)
{
    const float* x   = (const float*)d_in[0];
    const float* ea  = (const float*)d_in[1];
    const int*   ei  = (const int*)d_in[2];
    const float* W_e1 = (const float*)d_in[3];  const float* b_e1 = (const float*)d_in[4];
    const float* W_e2 = (const float*)d_in[5];  const float* b_e2 = (const float*)d_in[6];
    const float* W_e3 = (const float*)d_in[7];  const float* b_e3 = (const float*)d_in[8];
    const float* W_d1 = (const float*)d_in[9];  const float* b_d1 = (const float*)d_in[10];
    const float* W_d2 = (const float*)d_in[11]; const float* b_d2 = (const float*)d_in[12];
    const float* W_d3 = (const float*)d_in[13]; const float* b_d3 = (const float*)d_in[14];
    const float* W_s1 = (const float*)d_in[15]; const float* b_s1 = (const float*)d_in[16];
    const float* W_s2 = (const float*)d_in[17]; const float* b_s2 = (const float*)d_in[18];

    float* out = (float*)d_out;
    // Output layout: encoded [E,32] | reconstructed [E,192] | triplets [E,192] | scores [E,1]
    float* enc_out   = out;
    float* rec_out   = out + 32LL  * N_EDGES_C;
    float* trip_out  = out + 224LL * N_EDGES_C;
    float* score_out = out + 416LL * N_EDGES_C;

    cudaFuncSetAttribute(gnn_fused_kernel,
                         cudaFuncAttributeMaxDynamicSharedMemorySize, SMEM_BYTES);

    const int n_tiles = N_EDGES_C / TILE_E;  // 15625
    gnn_fused_kernel<<<n_tiles, 128, SMEM_BYTES>>>(
        x, ea, ei,
        W_e1, b_e1, W_e2, b_e2, W_e3, b_e3,
        W_d1, b_d1, W_d2, b_d2, W_d3, b_d3,
        W_s1, b_s1, W_s2, b_s2,
        enc_out, rec_out, trip_out, score_out);
}

// round 17
// speedup vs baseline: 2.4102x; 2.4102x over previous
#include <cuda_runtime.h>
#include <cuda_fp16.h>
#include <math.h>
#include <stdint.h>

#define N_EDGES_C 1000000
#define TILE_E 64
#define WPITCH 200   // weight-plane k-pitch (halves)

// fp16 hi/lo weight planes, transposed [N][WPITCH]: g_wt?[L][n*WPITCH + k]
__device__ __align__(16) __half g_wth[6][192 * WPITCH];
__device__ __align__(16) __half g_wtl[6][192 * WPITCH];

// smem: P0 planes (pitch 200), P1 planes (pitch 136), fp32 ENC scratch
#define P0_PITCH 200
#define P1_PITCH 136
#define P0_BYTES (2 * 64 * P0_PITCH * 2)   // 51200
#define P1_BYTES (2 * 64 * P1_PITCH * 2)   // 34816
#define SCR_OFF  (P0_BYTES + P1_BYTES)
#define SCR_PITCH 36
#define SMEM_BYTES (SCR_OFF + 64 * SCR_PITCH * 4)   // 95232

__device__ __forceinline__ unsigned pack_h2(__half a, __half b) {
    __half2 h = __halves2half2(a, b);
    return *reinterpret_cast<unsigned*>(&h);
}
__device__ __forceinline__ void split(float v, __half& hi, __half& lo) {
    hi = __float2half(v);
    lo = __float2half(v - __half2float(hi));
}
__device__ __forceinline__ void mma16816(float* d, const unsigned* a,
                                         unsigned b0, unsigned b1) {
    asm volatile(
        "mma.sync.aligned.m16n8k16.row.col.f32.f16.f16.f32 "
        "{%0,%1,%2,%3}, {%4,%5,%6,%7}, {%8,%9}, {%0,%1,%2,%3};"
        : "+f"(d[0]), "+f"(d[1]), "+f"(d[2]), "+f"(d[3])
        : "r"(a[0]), "r"(a[1]), "r"(a[2]), "r"(a[3]), "r"(b0), "r"(b1));
}

// ---- weight prep: W[K][N] fp32 -> g_wth/g_wtl [N][WPITCH] fp16 hi/lo ------
__global__ void prep_kernel(const float* __restrict__ W0, const float* __restrict__ W1,
                            const float* __restrict__ W2, const float* __restrict__ W3,
                            const float* __restrict__ W4, const float* __restrict__ W5) {
    const int L = blockIdx.x;
    const float* W; int K, N;
    switch (L) {
        case 0: W = W0; K = 192; N = 128; break;
        case 1: W = W1; K = 128; N = 64;  break;
        case 2: W = W2; K = 64;  N = 32;  break;
        case 3: W = W3; K = 32;  N = 64;  break;
        case 4: W = W4; K = 64;  N = 128; break;
        default:W = W5; K = 128; N = 192; break;
    }
    for (int i = threadIdx.x; i < K * N; i += blockDim.x) {
        const int k = i / N, n = i % N;
        const float w = W[i];
        __half h, l; split(w, h, l);
        g_wth[L][n * WPITCH + k] = h;
        g_wtl[L][n * WPITCH + k] = l;
    }
}

// ---- one MLP layer on the HMMA path ---------------------------------------
// inH/inL: fp16 planes [64][PIN]; wtH/wtL: [N][WPITCH]; out planes [64][POUT].
// Warp w: strips m0=32*(w&1)+{0,16}; n-tiles [ (w>>1)*NT/4, +NT/4 ).
template<int K, int N, int PIN, int POUT, bool RELU, bool SMOUT, bool GOUT, bool SCRW>
__device__ __forceinline__ void mma_layer(
    const __half* __restrict__ inH, const __half* __restrict__ inL,
    const __half* __restrict__ wtH, const __half* __restrict__ wtL,
    const float* __restrict__ bias,
    __half* __restrict__ outH, __half* __restrict__ outL,
    float* __restrict__ gout, float* __restrict__ scr, int tid)
{
    constexpr int NT4 = N / 32;          // n-tiles per warp
    const int w = tid >> 5, lane = tid & 31;
    const int gid = lane >> 2, tig = lane & 3;
    const int m0 = (w & 1) * 32;
    const int nb0 = (w >> 1) * NT4 * 8;

    float acc[2][NT4][4];
#pragma unroll
    for (int s = 0; s < 2; ++s)
#pragma unroll
        for (int t = 0; t < NT4; ++t)
#pragma unroll
            for (int i = 0; i < 4; ++i) acc[s][t][i] = 0.0f;

#pragma unroll 2
    for (int ks = 0; ks < K / 16; ++ks) {
        const int kk = ks * 16;
        const int ca = kk + tig * 2;
        unsigned ah[2][4], al[2][4];
#pragma unroll
        for (int s = 0; s < 2; ++s) {
            const int r = m0 + s * 16 + gid;
            const __half* ph = inH + r * PIN + ca;
            const __half* pl = inL + r * PIN + ca;
            ah[s][0] = *(const unsigned*)(ph);
            ah[s][1] = *(const unsigned*)(ph + 8 * PIN);
            ah[s][2] = *(const unsigned*)(ph + 8);
            ah[s][3] = *(const unsigned*)(ph + 8 * PIN + 8);
            al[s][0] = *(const unsigned*)(pl);
            al[s][1] = *(const unsigned*)(pl + 8 * PIN);
            al[s][2] = *(const unsigned*)(pl + 8);
            al[s][3] = *(const unsigned*)(pl + 8 * PIN + 8);
        }
#pragma unroll
        for (int t = 0; t < NT4; ++t) {
            const int n = nb0 + t * 8 + gid;
            const __half* pwh = wtH + n * WPITCH + ca;
            const __half* pwl = wtL + n * WPITCH + ca;
            const unsigned bh0 = *(const unsigned*)(pwh);
            const unsigned bh1 = *(const unsigned*)(pwh + 8);
            const unsigned bl0 = *(const unsigned*)(pwl);
            const unsigned bl1 = *(const unsigned*)(pwl + 8);
#pragma unroll
            for (int s = 0; s < 2; ++s) {
                mma16816(acc[s][t], ah[s], bh0, bh1);
                mma16816(acc[s][t], al[s], bh0, bh1);
                mma16816(acc[s][t], ah[s], bl0, bl1);
            }
        }
    }

    // epilogue: bias (+relu), then store
#pragma unroll
    for (int s = 0; s < 2; ++s) {
        const int r = m0 + s * 16 + gid;
#pragma unroll
        for (int t = 0; t < NT4; ++t) {
            const int c = nb0 + t * 8 + tig * 2;
            const float b0 = __ldg(bias + c), b1 = __ldg(bias + c + 1);
            float v0 = acc[s][t][0] + b0, v1 = acc[s][t][1] + b1;
            float v2 = acc[s][t][2] + b0, v3 = acc[s][t][3] + b1;
            if (RELU) {
                v0 = fmaxf(v0, 0.f); v1 = fmaxf(v1, 0.f);
                v2 = fmaxf(v2, 0.f); v3 = fmaxf(v3, 0.f);
            }
            if (SMOUT) {
                __half h0, l0, h1, l1;
                split(v0, h0, l0); split(v1, h1, l1);
                *(unsigned*)(outH + r * POUT + c) = pack_h2(h0, h1);
                *(unsigned*)(outL + r * POUT + c) = pack_h2(l0, l1);
                split(v2, h0, l0); split(v3, h1, l1);
                *(unsigned*)(outH + (r + 8) * POUT + c) = pack_h2(h0, h1);
                *(unsigned*)(outL + (r + 8) * POUT + c) = pack_h2(l0, l1);
            }
            if (GOUT) {
                *(float2*)(gout + (size_t)r * N + c) = make_float2(v0, v1);
                *(float2*)(gout + (size_t)(r + 8) * N + c) = make_float2(v2, v3);
            }
            if (SCRW) {
                scr[r * SCR_PITCH + c] = v0;       scr[r * SCR_PITCH + c + 1] = v1;
                scr[(r + 8) * SCR_PITCH + c] = v2; scr[(r + 8) * SCR_PITCH + c + 1] = v3;
            }
        }
    }
}

__global__ void __launch_bounds__(256, 2)
gnn_mma_kernel(
    const float* __restrict__ x,
    const float* __restrict__ ea,
    const int* __restrict__ ei,     // int32 (jax default)
    const float* __restrict__ b_e1, const float* __restrict__ b_e2,
    const float* __restrict__ b_e3, const float* __restrict__ b_d1,
    const float* __restrict__ b_d2, const float* __restrict__ b_d3,
    const float* __restrict__ W_s1, const float* __restrict__ b_s1,
    const float* __restrict__ W_s2, const float* __restrict__ b_s2,
    float* __restrict__ enc_out, float* __restrict__ rec_out,
    float* __restrict__ trip_out, float* __restrict__ score_out)
{
    extern __shared__ char smem[];
    __half* P0H = (__half*)smem;
    __half* P0L = P0H + 64 * P0_PITCH;
    __half* P1H = (__half*)(smem + P0_BYTES);
    __half* P1L = P1H + 64 * P1_PITCH;
    float*  scr = (float*)(smem + SCR_OFF);

    const int tid = threadIdx.x;
    const long long ebase = (long long)blockIdx.x * TILE_E;

    // ---- Gather: triplets -> trip_out (fp32) + P0 hi/lo planes (edge-major)
    {
        const int el = tid >> 2;   // edge in tile
        const int r  = tid & 3;    // 4 threads/edge, 12 float4 each
        const long long eg = ebase + el;
        const int s = __ldg(ei + eg);
        const int d = __ldg(ei + N_EDGES_C + eg);
        const float4* srcp = (const float4*)(x + (size_t)s * 64);
        const float4* eap  = (const float4*)(ea + (size_t)eg * 64);
        const float4* dstp = (const float4*)(x + (size_t)d * 64);
        float* top = trip_out + (size_t)eg * 192;
#pragma unroll
        for (int m = 0; m < 12; ++m) {
            const int q = r * 12 + m;
            float4 v;
            if (q < 16)      v = __ldg(srcp + q);
            else if (q < 32) v = __ldg(eap + (q - 16));
            else             v = __ldg(dstp + (q - 32));
            const int k = q * 4;
            *(float4*)(top + k) = v;
            __half h0, l0, h1, l1, h2, l2, h3, l3;
            split(v.x, h0, l0); split(v.y, h1, l1);
            split(v.z, h2, l2); split(v.w, h3, l3);
            *(unsigned*)(P0H + el * P0_PITCH + k)     = pack_h2(h0, h1);
            *(unsigned*)(P0H + el * P0_PITCH + k + 2) = pack_h2(h2, h3);
            *(unsigned*)(P0L + el * P0_PITCH + k)     = pack_h2(l0, l1);
            *(unsigned*)(P0L + el * P0_PITCH + k + 2) = pack_h2(l2, l3);
        }
    }
    __syncthreads();

    // e1: 192->128, P0 -> P1
    mma_layer<192, 128, P0_PITCH, P1_PITCH, true,  true,  false, false>(
        P0H, P0L, g_wth[0], g_wtl[0], b_e1, P1H, P1L, nullptr, nullptr, tid);
    __syncthreads();
    // e2: 128->64, P1 -> P0
    mma_layer<128, 64, P1_PITCH, P0_PITCH, true,  true,  false, false>(
        P1H, P1L, g_wth[1], g_wtl[1], b_e2, P0H, P0L, nullptr, nullptr, tid);
    __syncthreads();
    // e3: 64->32, P0 -> P1 (+ enc_out + scr)
    mma_layer<64, 32, P0_PITCH, P1_PITCH, false, true,  true,  true>(
        P0H, P0L, g_wth[2], g_wtl[2], b_e3, P1H, P1L,
        enc_out + ebase * 32, scr, tid);
    __syncthreads();
    // d1: 32->64, P1 -> P0
    mma_layer<32, 64, P1_PITCH, P0_PITCH, true,  true,  false, false>(
        P1H, P1L, g_wth[3], g_wtl[3], b_d1, P0H, P0L, nullptr, nullptr, tid);
    __syncthreads();
    // d2: 64->128, P0 -> P1
    mma_layer<64, 128, P0_PITCH, P1_PITCH, true,  true,  false, false>(
        P0H, P0L, g_wth[4], g_wtl[4], b_d2, P1H, P1L, nullptr, nullptr, tid);
    __syncthreads();
    // d3: 128->192, P1 -> rec_out (no planes)
    mma_layer<128, 192, P1_PITCH, P0_PITCH, false, false, true,  false>(
        P1H, P1L, g_wth[5], g_wtl[5], b_d3, nullptr, nullptr,
        rec_out + ebase * 192, nullptr, tid);

    // ---- Scorer (scr untouched since e3; no barrier needed after d3 writes gmem,
    //      but scr was written pre-d1-sync, so it's visible)
    if (tid < TILE_E) {
        float e[32];
#pragma unroll
        for (int k = 0; k < 32; ++k)
            e[k] = scr[tid * SCR_PITCH + k];
        float acc = __ldg(b_s2);
#pragma unroll
        for (int j = 0; j < 16; ++j) {
            float hs = __ldg(b_s1 + j);
#pragma unroll
            for (int k = 0; k < 32; ++k)
                hs += e[k] * __ldg(W_s1 + k * 16 + j);
            hs = fmaxf(hs, 0.0f);
            acc += hs * __ldg(W_s2 + j);
        }
        score_out[ebase + tid] = 1.0f / (1.0f + expf(-acc));
    }
}

extern "C" void kernel_launch(void* const* d_in, const int* in_sizes, int n_in,
                              void* d_out, int out_size)
{
    const float* x   = (const float*)d_in[0];
    const float* ea  = (const float*)d_in[1];
    const int*   ei  = (const int*)d_in[2];
    const float* W_e1 = (const float*)d_in[3];  const float* b_e1 = (const float*)d_in[4];
    const float* W_e2 = (const float*)d_in[5];  const float* b_e2 = (const float*)d_in[6];
    const float* W_e3 = (const float*)d_in[7];  const float* b_e3 = (const float*)d_in[8];
    const float* W_d1 = (const float*)d_in[9];  const float* b_d1 = (const float*)d_in[10];
    const float* W_d2 = (const float*)d_in[11]; const float* b_d2 = (const float*)d_in[12];
    const float* W_d3 = (const float*)d_in[13]; const float* b_d3 = (const float*)d_in[14];
    const float* W_s1 = (const float*)d_in[15]; const float* b_s1 = (const float*)d_in[16];
    const float* W_s2 = (const float*)d_in[17]; const float* b_s2 = (const float*)d_in[18];

    float* out = (float*)d_out;
    float* enc_out   = out;
    float* rec_out   = out + 32LL  * N_EDGES_C;
    float* trip_out  = out + 224LL * N_EDGES_C;
    float* score_out = out + 416LL * N_EDGES_C;

    prep_kernel<<<6, 256>>>(W_e1, W_e2, W_e3, W_d1, W_d2, W_d3);

    cudaFuncSetAttribute(gnn_mma_kernel,
                         cudaFuncAttributeMaxDynamicSharedMemorySize, SMEM_BYTES);
    const int n_tiles = N_EDGES_C / TILE_E;  // 15625
    gnn_mma_kernel<<<n_tiles, 256, SMEM_BYTES>>>(
        x, ea, ei,
        b_e1, b_e2, b_e3, b_d1, b_d2, b_d3,
        W_s1, b_s1, W_s2, b_s2,
        enc_out, rec_out, trip_out, score_out);
}